// round 2
// baseline (speedup 1.0000x reference)
#include <cuda_runtime.h>
#include <math.h>

#define B   64
#define D   128
#define LC  1024
#define LQ  256
#define NEG_INF -1e30f

typedef unsigned long long ull;

// packed fp32x2 FMA: acc.lo += a.lo*b.lo ; acc.hi += a.hi*b.hi  (FFMA2, sm_100+)
__device__ __forceinline__ void ffma2(ull& acc, ull a, ull b) {
    asm("fma.rn.f32x2 %0, %1, %2, %0;" : "+l"(acc) : "l"(a), "l"(b));
}
__device__ __forceinline__ float lo32(ull v) { return __uint_as_float((unsigned)v); }
__device__ __forceinline__ float hi32(ull v) { return __uint_as_float((unsigned)(v >> 32)); }

// ---------------- scratch (device globals: no allocation allowed) ----------------
__device__ float g_E[(size_t)B * LC * LQ];   // exp(S), 64 MiB
__device__ float g_M[(size_t)B * LQ * D];    // S2^T @ Ct
__device__ float g_rowsum[B * LC];
__device__ float g_colsum[B * LQ];
__device__ float g_cw1[B * LC];
__device__ float g_qw2[B * LQ];
__device__ float g_fc[B * LC];               // exp((1-cmask)*NEG_INF)  (0 or 1)
__device__ float g_fq[B * LQ];               // exp((1-qmask)*NEG_INF)

// ---------------- K0: biases, mask factors, zero accumulators ----------------
__global__ void k0_setup(const float* __restrict__ C, const float* __restrict__ Q,
                         const float* __restrict__ cmask, const float* __restrict__ qmask,
                         const float* __restrict__ w) {
    int idx = blockIdx.x * 256 + threadIdx.x;
    if (idx < B * LC) {
        int b = idx >> 10;
        int i = idx & (LC - 1);
        const float* cp = C + (size_t)b * D * LC + i;
        float s = 0.f;
#pragma unroll 4
        for (int dd = 0; dd < D; ++dd) s = fmaf(cp[(size_t)dd * LC], w[dd], s);
        g_cw1[idx] = s;
        g_fc[idx] = expf((1.0f - cmask[idx]) * NEG_INF);
        g_rowsum[idx] = 0.f;
    } else {
        int t = idx - B * LC;
        if (t < B * LQ) {
            int b = t >> 8;
            int j = t & (LQ - 1);
            const float* qp = Q + (size_t)b * D * LQ + j;
            float s = 0.f;
#pragma unroll 4
            for (int dd = 0; dd < D; ++dd) s = fmaf(qp[(size_t)dd * LQ], w[D + dd], s);
            g_qw2[t] = s;
            g_fq[t] = expf((1.0f - qmask[t]) * NEG_INF);
            g_colsum[t] = 0.f;
        }
    }
}

// ---------------- K1: E = exp(S) + row/col exp-sums -------------------------
// grid (LQ/64, LC/64, B), 256 threads, 64x64 tile, micro 4x4 (FFMA2-packed on j)
__global__ __launch_bounds__(256) void k1_score(const float* __restrict__ C,
                                                const float* __restrict__ Q,
                                                const float* __restrict__ w) {
    int b = blockIdx.z;
    int i0 = blockIdx.y * 64;
    int j0 = blockIdx.x * 64;

    __shared__ float As2[16][128];   // duplicated: As2[k][2i]=As2[k][2i+1]=C*w3
    __shared__ float Bs[16][64];     // Q
    __shared__ float srow[64];
    __shared__ float scol[64];

    int tid = threadIdx.x;
    int tm = tid & 15;      // row group (i)
    int tn = tid >> 4;      // col group (j)
    if (tid < 64) { srow[tid] = 0.f; scol[tid] = 0.f; }

    ull acc2[4][2];
#pragma unroll
    for (int r = 0; r < 4; ++r) { acc2[r][0] = 0ull; acc2[r][1] = 0ull; }

    const float* Cb = C + (size_t)b * D * LC;
    const float* Qb = Q + (size_t)b * D * LQ;

    int t4 = tid * 4;
    int lkk = t4 >> 6;      // 0..15
    int lii = t4 & 63;      // 0..60 step 4

    for (int k0 = 0; k0 < D; k0 += 16) {
        float w3v = w[2 * D + k0 + lkk];
        float4 v = *(const float4*)(Cb + (size_t)(k0 + lkk) * LC + i0 + lii);
        v.x *= w3v; v.y *= w3v; v.z *= w3v; v.w *= w3v;
        float4 u = *(const float4*)(Qb + (size_t)(k0 + lkk) * LQ + j0 + lii);
        __syncthreads();
        *(float4*)&As2[lkk][2 * lii]     = make_float4(v.x, v.x, v.y, v.y);
        *(float4*)&As2[lkk][2 * lii + 4] = make_float4(v.z, v.z, v.w, v.w);
        *(float4*)&Bs[lkk][lii] = u;
        __syncthreads();
#pragma unroll
        for (int kk = 0; kk < 16; ++kk) {
            ulonglong2 a01 = *(const ulonglong2*)&As2[kk][tm * 8];      // (a0,a0),(a1,a1)
            ulonglong2 a23 = *(const ulonglong2*)&As2[kk][tm * 8 + 4];  // (a2,a2),(a3,a3)
            ulonglong2 bp  = *(const ulonglong2*)&Bs[kk][tn * 4];       // (b0,b1),(b2,b3)
            ffma2(acc2[0][0], a01.x, bp.x); ffma2(acc2[0][1], a01.x, bp.y);
            ffma2(acc2[1][0], a01.y, bp.x); ffma2(acc2[1][1], a01.y, bp.y);
            ffma2(acc2[2][0], a23.x, bp.x); ffma2(acc2[2][1], a23.x, bp.y);
            ffma2(acc2[3][0], a23.y, bp.x); ffma2(acc2[3][1], a23.y, bp.y);
        }
    }

    // epilogue: biases, exp, store E, reduce row/col sums
    int ib = i0 + tm * 4;
    int jb = j0 + tn * 4;
    float cw[4], fcv[4], qw[4], fqv[4];
#pragma unroll
    for (int r = 0; r < 4; ++r) { cw[r] = g_cw1[b * LC + ib + r]; fcv[r] = g_fc[b * LC + ib + r]; }
#pragma unroll
    for (int c = 0; c < 4; ++c) { qw[c] = g_qw2[b * LQ + jb + c]; fqv[c] = g_fq[b * LQ + jb + c]; }

    float rowp[4] = {0.f, 0.f, 0.f, 0.f};
    float colp[4] = {0.f, 0.f, 0.f, 0.f};
    float ev[4][4];
#pragma unroll
    for (int r = 0; r < 4; ++r) {
#pragma unroll
        for (int c = 0; c < 4; ++c) {
            float s = ((c & 1) ? hi32(acc2[r][c >> 1]) : lo32(acc2[r][c >> 1]));
            float e = expf(s + cw[r] + qw[c]);
            ev[r][c] = e;
            rowp[r] = fmaf(e, fqv[c], rowp[r]);
            colp[c] = fmaf(e, fcv[r], colp[c]);
        }
    }
#pragma unroll
    for (int r = 0; r < 4; ++r) {
        *(float4*)(g_E + ((size_t)b * LC + ib + r) * LQ + jb) =
            make_float4(ev[r][0], ev[r][1], ev[r][2], ev[r][3]);
    }
#pragma unroll
    for (int r = 0; r < 4; ++r) atomicAdd(&srow[tm * 4 + r], rowp[r]);
#pragma unroll
    for (int c = 0; c < 4; ++c) atomicAdd(&scol[tn * 4 + c], colp[c]);
    __syncthreads();
    if (tid < 64)       atomicAdd(&g_rowsum[b * LC + i0 + tid], srow[tid]);
    else if (tid < 128) atomicAdd(&g_colsum[b * LQ + j0 + tid - 64], scol[tid - 64]);
}

// ---------------- K4: M[b,j,dd] = (sum_i E[i,j]*fc[i]*C[dd,i]) / colsum[j] ---
// grid (D/64, LQ/64, B), K = LC = 1024
__global__ __launch_bounds__(256) void k4_m(const float* __restrict__ C) {
    int b = blockIdx.z;
    int j0 = blockIdx.y * 64;
    int dd0 = blockIdx.x * 64;

    __shared__ float As2[16][128];  // duplicated E*fc  [kk=i][2*j..]
    __shared__ float Bs[16][64];    // C transposed     [kk=i][dd]

    int tid = threadIdx.x;
    int tm = tid & 15;   // j group
    int tn = tid >> 4;   // dd group

    ull acc2[4][2];
#pragma unroll
    for (int r = 0; r < 4; ++r) { acc2[r][0] = 0ull; acc2[r][1] = 0ull; }

    const float* Cb = C + (size_t)b * D * LC;
    const float* Eb = g_E + (size_t)b * LC * LQ;

    int t4 = tid * 4;
    int akk = t4 >> 6, amb = t4 & 63;        // direct load (E)
    int bnr = tid >> 2, bkb = (tid & 3) * 4; // transpose load (C)

    for (int k0 = 0; k0 < LC; k0 += 16) {
        float fcv = g_fc[b * LC + k0 + akk];
        float4 v = *(const float4*)(Eb + (size_t)(k0 + akk) * LQ + j0 + amb);
        v.x *= fcv; v.y *= fcv; v.z *= fcv; v.w *= fcv;
        float4 u = *(const float4*)(Cb + (size_t)(dd0 + bnr) * LC + k0 + bkb);
        __syncthreads();
        *(float4*)&As2[akk][2 * amb]     = make_float4(v.x, v.x, v.y, v.y);
        *(float4*)&As2[akk][2 * amb + 4] = make_float4(v.z, v.z, v.w, v.w);
        Bs[bkb + 0][bnr] = u.x;
        Bs[bkb + 1][bnr] = u.y;
        Bs[bkb + 2][bnr] = u.z;
        Bs[bkb + 3][bnr] = u.w;
        __syncthreads();
#pragma unroll
        for (int kk = 0; kk < 16; ++kk) {
            ulonglong2 a01 = *(const ulonglong2*)&As2[kk][tm * 8];
            ulonglong2 a23 = *(const ulonglong2*)&As2[kk][tm * 8 + 4];
            ulonglong2 bp  = *(const ulonglong2*)&Bs[kk][tn * 4];
            ffma2(acc2[0][0], a01.x, bp.x); ffma2(acc2[0][1], a01.x, bp.y);
            ffma2(acc2[1][0], a01.y, bp.x); ffma2(acc2[1][1], a01.y, bp.y);
            ffma2(acc2[2][0], a23.x, bp.x); ffma2(acc2[2][1], a23.x, bp.y);
            ffma2(acc2[3][0], a23.y, bp.x); ffma2(acc2[3][1], a23.y, bp.y);
        }
    }

    float cinv[4];
#pragma unroll
    for (int r = 0; r < 4; ++r) cinv[r] = 1.0f / g_colsum[b * LQ + j0 + tm * 4 + r];
#pragma unroll
    for (int r = 0; r < 4; ++r) {
        float4 m4 = make_float4(lo32(acc2[r][0]) * cinv[r], hi32(acc2[r][0]) * cinv[r],
                                lo32(acc2[r][1]) * cinv[r], hi32(acc2[r][1]) * cinv[r]);
        *(float4*)(g_M + ((size_t)b * LQ + j0 + tm * 4 + r) * D + dd0 + tn * 4) = m4;
    }
}

// ---------------- K5: A & Bmat fused + all 4 output channels -----------------
// grid (D/64, LC/64, B), K = LQ = 256
__global__ __launch_bounds__(256) void k5_out(const float* __restrict__ C,
                                              const float* __restrict__ Q,
                                              float* __restrict__ out) {
    int b = blockIdx.z;
    int i0 = blockIdx.y * 64;
    int dd0 = blockIdx.x * 64;

    __shared__ float As2[16][128];  // duplicated E*fq [kk=j][2*i..]
    __shared__ float Bq[16][64];    // Q  [kk=j][dd]
    __shared__ float Bm[16][64];    // M  [kk=j][dd]
    __shared__ float fqs[LQ];

    int tid = threadIdx.x;
    int tm = tid & 15;   // i group
    int tn = tid >> 4;   // dd group
    fqs[tid] = g_fq[b * LQ + tid];

    ull accA2[4][2], accB2[4][2];
#pragma unroll
    for (int r = 0; r < 4; ++r) {
        accA2[r][0] = 0ull; accA2[r][1] = 0ull;
        accB2[r][0] = 0ull; accB2[r][1] = 0ull;
    }

    const float* Cb = C + (size_t)b * D * LC;
    const float* Qb = Q + (size_t)b * D * LQ;
    const float* Eb = g_E + (size_t)b * LC * LQ;
    const float* Mb = g_M + (size_t)b * LQ * D;

    int anr = tid >> 2, akb = (tid & 3) * 4;        // transpose loads (E, Q)
    int bkk = (tid * 4) >> 6, bnb = (tid * 4) & 63; // direct load (M)

    for (int k0 = 0; k0 < LQ; k0 += 16) {
        float4 ev = *(const float4*)(Eb + (size_t)(i0 + anr) * LQ + k0 + akb);
        float4 qv = *(const float4*)(Qb + (size_t)(dd0 + anr) * LQ + k0 + akb);
        float4 mv = *(const float4*)(Mb + (size_t)(k0 + bkk) * D + dd0 + bnb);
        __syncthreads();
        {
            float e0 = ev.x * fqs[k0 + akb + 0];
            float e1 = ev.y * fqs[k0 + akb + 1];
            float e2 = ev.z * fqs[k0 + akb + 2];
            float e3 = ev.w * fqs[k0 + akb + 3];
            As2[akb + 0][2 * anr] = e0; As2[akb + 0][2 * anr + 1] = e0;
            As2[akb + 1][2 * anr] = e1; As2[akb + 1][2 * anr + 1] = e1;
            As2[akb + 2][2 * anr] = e2; As2[akb + 2][2 * anr + 1] = e2;
            As2[akb + 3][2 * anr] = e3; As2[akb + 3][2 * anr + 1] = e3;
        }
        Bq[akb + 0][anr] = qv.x;
        Bq[akb + 1][anr] = qv.y;
        Bq[akb + 2][anr] = qv.z;
        Bq[akb + 3][anr] = qv.w;
        *(float4*)&Bm[bkk][bnb] = mv;
        __syncthreads();
#pragma unroll
        for (int kk = 0; kk < 16; ++kk) {
            ulonglong2 a01 = *(const ulonglong2*)&As2[kk][tm * 8];
            ulonglong2 a23 = *(const ulonglong2*)&As2[kk][tm * 8 + 4];
            ulonglong2 qp  = *(const ulonglong2*)&Bq[kk][tn * 4];
            ulonglong2 mp  = *(const ulonglong2*)&Bm[kk][tn * 4];
            ffma2(accA2[0][0], a01.x, qp.x); ffma2(accA2[0][1], a01.x, qp.y);
            ffma2(accA2[1][0], a01.y, qp.x); ffma2(accA2[1][1], a01.y, qp.y);
            ffma2(accA2[2][0], a23.x, qp.x); ffma2(accA2[2][1], a23.x, qp.y);
            ffma2(accA2[3][0], a23.y, qp.x); ffma2(accA2[3][1], a23.y, qp.y);
            ffma2(accB2[0][0], a01.x, mp.x); ffma2(accB2[0][1], a01.x, mp.y);
            ffma2(accB2[1][0], a01.y, mp.x); ffma2(accB2[1][1], a01.y, mp.y);
            ffma2(accB2[2][0], a23.x, mp.x); ffma2(accB2[2][1], a23.x, mp.y);
            ffma2(accB2[3][0], a23.y, mp.x); ffma2(accB2[3][1], a23.y, mp.y);
        }
    }

    float rinv[4];
#pragma unroll
    for (int r = 0; r < 4; ++r) rinv[r] = 1.0f / g_rowsum[b * LC + i0 + tm * 4 + r];

    size_t ob = (size_t)b * 4 * D * LC;
    int i = i0 + tm * 4;
#pragma unroll
    for (int c = 0; c < 4; ++c) {
        int dd = dd0 + tn * 4 + c;
        float4 c4 = *(const float4*)(Cb + (size_t)dd * LC + i);
        float aAr[4], aBr[4];
#pragma unroll
        for (int r = 0; r < 4; ++r) {
            aAr[r] = ((c & 1) ? hi32(accA2[r][c >> 1]) : lo32(accA2[r][c >> 1])) * rinv[r];
            aBr[r] = ((c & 1) ? hi32(accB2[r][c >> 1]) : lo32(accB2[r][c >> 1])) * rinv[r];
        }
        float4 a4 = make_float4(aAr[0], aAr[1], aAr[2], aAr[3]);
        float4 b4 = make_float4(aBr[0], aBr[1], aBr[2], aBr[3]);
        *(float4*)(out + ob + (size_t)dd * LC + i) = c4;                              // Ct
        *(float4*)(out + ob + (size_t)(D + dd) * LC + i) = a4;                        // A
        *(float4*)(out + ob + (size_t)(2 * D + dd) * LC + i) =
            make_float4(c4.x * a4.x, c4.y * a4.y, c4.z * a4.z, c4.w * a4.w);          // Ct*A
        *(float4*)(out + ob + (size_t)(3 * D + dd) * LC + i) =
            make_float4(c4.x * b4.x, c4.y * b4.y, c4.z * b4.z, c4.w * b4.w);          // Ct*Bmat
    }
}

// ---------------- launch ------------------------------------------------------
extern "C" void kernel_launch(void* const* d_in, const int* in_sizes, int n_in,
                              void* d_out, int out_size) {
    const float* C = (const float*)d_in[0];
    const float* Q = (const float*)d_in[1];
    const float* cmask = (const float*)d_in[2];
    const float* qmask = (const float*)d_in[3];
    const float* w = (const float*)d_in[4];
    float* out = (float*)d_out;

    k0_setup<<<(B * LC + B * LQ) / 256, 256>>>(C, Q, cmask, qmask, w);

    dim3 g1(LQ / 64, LC / 64, B);
    k1_score<<<g1, 256>>>(C, Q, w);

    dim3 g4(D / 64, LQ / 64, B);
    k4_m<<<g4, 256>>>(C);

    dim3 g5(D / 64, LC / 64, B);
    k5_out<<<g5, 256>>>(C, Q, out);
}

// round 3
// speedup vs baseline: 1.9335x; 1.9335x over previous
#include <cuda_runtime.h>
#include <math.h>

#define B    64
#define D    128
#define LC   1024
#define LQ   256
#define NEG_INF -1e30f
#define TS   128      // CTA tile (M and N)
#define KC   8        // K chunk
#define PADW 132      // padded smem row (floats)

// ---------------- scratch (device globals: no allocation allowed) ----------------
__device__ float g_E[(size_t)B * LC * LQ];   // exp(S), 64 MiB
__device__ float g_M[(size_t)B * LQ * D];    // S2^T @ Ct
__device__ float g_rowsum[B * LC];
__device__ float g_colsum[B * LQ];
__device__ float g_cw1[B * LC];
__device__ float g_qw2[B * LQ];
__device__ float g_fc[B * LC];               // exp((1-cmask)*NEG_INF)  (0 or 1)
__device__ float g_fq[B * LQ];               // exp((1-qmask)*NEG_INF)

// ---------------- K0: biases, mask factors, zero accumulators ----------------
__global__ void k0_setup(const float* __restrict__ C, const float* __restrict__ Q,
                         const float* __restrict__ cmask, const float* __restrict__ qmask,
                         const float* __restrict__ w) {
    int idx = blockIdx.x * 256 + threadIdx.x;
    if (idx < B * LC) {
        int b = idx >> 10;
        int i = idx & (LC - 1);
        const float* cp = C + (size_t)b * D * LC + i;
        float s = 0.f;
#pragma unroll 4
        for (int dd = 0; dd < D; ++dd) s = fmaf(cp[(size_t)dd * LC], w[dd], s);
        g_cw1[idx] = s;
        g_fc[idx] = expf((1.0f - cmask[idx]) * NEG_INF);
        g_rowsum[idx] = 0.f;
    } else {
        int t = idx - B * LC;
        if (t < B * LQ) {
            int b = t >> 8;
            int j = t & (LQ - 1);
            const float* qp = Q + (size_t)b * D * LQ + j;
            float s = 0.f;
#pragma unroll 4
            for (int dd = 0; dd < D; ++dd) s = fmaf(qp[(size_t)dd * LQ], w[D + dd], s);
            g_qw2[t] = s;
            g_fq[t] = expf((1.0f - qmask[t]) * NEG_INF);
            g_colsum[t] = 0.f;
        }
    }
}

// ---------------- K1: E = exp(S) + row/col exp-sums -------------------------
// grid (LQ/128, LC/128, B), 256 thr, 128x128 tile, 8x8 micro, K=D=128
__global__ __launch_bounds__(256) void k1_score(const float* __restrict__ C,
                                                const float* __restrict__ Q,
                                                const float* __restrict__ w) {
    int b = blockIdx.z;
    int i0 = blockIdx.y * TS;
    int j0 = blockIdx.x * TS;

    __shared__ float As[KC][PADW];   // [k=d][i]  C*w3
    __shared__ float Bs[KC][PADW];   // [k=d][j]  Q
    __shared__ float srow[TS], scol[TS];

    int tid = threadIdx.x;
    int tm = tid & 15;      // i group
    int tn = tid >> 4;      // j group
    if (tid < TS) srow[tid] = 0.f; else scol[tid - TS] = 0.f;

    float acc[8][8];
#pragma unroll
    for (int r = 0; r < 8; ++r)
#pragma unroll
        for (int c = 0; c < 8; ++c) acc[r][c] = 0.f;

    const float* Cb = C + (size_t)b * D * LC;
    const float* Qb = Q + (size_t)b * D * LQ;

    int lr = tid >> 5;          // 0..7 (k within chunk)
    int lc = (tid & 31) * 4;    // 0..124

    float4 va, vb;
    {   // prefetch chunk 0
        float w3v = w[2 * D + lr];
        va = *(const float4*)(Cb + (size_t)lr * LC + i0 + lc);
        va.x *= w3v; va.y *= w3v; va.z *= w3v; va.w *= w3v;
        vb = *(const float4*)(Qb + (size_t)lr * LQ + j0 + lc);
    }

    for (int k0 = 0; k0 < D; k0 += KC) {
        __syncthreads();
        *(float4*)&As[lr][lc] = va;
        *(float4*)&Bs[lr][lc] = vb;
        __syncthreads();
        if (k0 + KC < D) {
            float w3v = w[2 * D + k0 + KC + lr];
            va = *(const float4*)(Cb + (size_t)(k0 + KC + lr) * LC + i0 + lc);
            va.x *= w3v; va.y *= w3v; va.z *= w3v; va.w *= w3v;
            vb = *(const float4*)(Qb + (size_t)(k0 + KC + lr) * LQ + j0 + lc);
        }
#pragma unroll
        for (int kk = 0; kk < KC; ++kk) {
            float av[8], bv[8];
            *(float4*)&av[0] = *(const float4*)&As[kk][tm * 4];
            *(float4*)&av[4] = *(const float4*)&As[kk][64 + tm * 4];
            *(float4*)&bv[0] = *(const float4*)&Bs[kk][tn * 4];
            *(float4*)&bv[4] = *(const float4*)&Bs[kk][64 + tn * 4];
#pragma unroll
            for (int r = 0; r < 8; ++r)
#pragma unroll
                for (int c = 0; c < 8; ++c) acc[r][c] = fmaf(av[r], bv[c], acc[r][c]);
        }
    }

    // ---- epilogue: biases, exp, store E, reduce row/col sums ----
    int il[8], jl[8];
#pragma unroll
    for (int t = 0; t < 4; ++t) {
        il[t] = tm * 4 + t;  il[4 + t] = 64 + tm * 4 + t;
        jl[t] = tn * 4 + t;  jl[4 + t] = 64 + tn * 4 + t;
    }
    float cw[8], fcv[8], qw[8], fqv[8];
#pragma unroll
    for (int r = 0; r < 8; ++r) { cw[r] = g_cw1[b * LC + i0 + il[r]]; fcv[r] = g_fc[b * LC + i0 + il[r]]; }
#pragma unroll
    for (int c = 0; c < 8; ++c) { qw[c] = g_qw2[b * LQ + j0 + jl[c]]; fqv[c] = g_fq[b * LQ + j0 + jl[c]]; }

    float rowp[8] = {0.f,0.f,0.f,0.f,0.f,0.f,0.f,0.f};
    float colp[8] = {0.f,0.f,0.f,0.f,0.f,0.f,0.f,0.f};
#pragma unroll
    for (int r = 0; r < 8; ++r) {
        float ev[8];
#pragma unroll
        for (int c = 0; c < 8; ++c) {
            float e = expf(acc[r][c] + cw[r] + qw[c]);
            ev[c] = e;
            rowp[r] = fmaf(e, fqv[c], rowp[r]);
            colp[c] = fmaf(e, fcv[r], colp[c]);
        }
        float* erow = g_E + ((size_t)b * LC + i0 + il[r]) * LQ + j0;
        *(float4*)(erow + tn * 4)      = make_float4(ev[0], ev[1], ev[2], ev[3]);
        *(float4*)(erow + 64 + tn * 4) = make_float4(ev[4], ev[5], ev[6], ev[7]);
    }
#pragma unroll
    for (int r = 0; r < 8; ++r) atomicAdd(&srow[il[r]], rowp[r]);
#pragma unroll
    for (int c = 0; c < 8; ++c) atomicAdd(&scol[jl[c]], colp[c]);
    __syncthreads();
    if (tid < TS) atomicAdd(&g_rowsum[b * LC + i0 + tid], srow[tid]);
    else          atomicAdd(&g_colsum[b * LQ + j0 + tid - TS], scol[tid - TS]);
}

// ---------------- K4: M[b,j,dd] = (sum_i E[i,j]*fc[i]*C[dd,i]) / colsum[j] ---
// grid (LQ/128, B), K = LC = 1024, N = D = 128 (full)
__global__ __launch_bounds__(256) void k4_m(const float* __restrict__ C) {
    int b = blockIdx.y;
    int j0 = blockIdx.x * TS;

    __shared__ float As[KC][PADW];   // [k=i][j]   E*fc
    __shared__ float Bs[KC][PADW];   // [k=i][dd]  C^T

    int tid = threadIdx.x;
    int tm = tid & 15;   // j group
    int tn = tid >> 4;   // dd group

    float acc[8][8];
#pragma unroll
    for (int r = 0; r < 8; ++r)
#pragma unroll
        for (int c = 0; c < 8; ++c) acc[r][c] = 0.f;

    const float* Cb = C + (size_t)b * D * LC;
    const float* Eb = g_E + (size_t)b * LC * LQ;

    int lr = tid >> 5, lc = (tid & 31) * 4;   // direct (E): row=i-in-chunk, col=j
    int bd = tid >> 1, bk = (tid & 1) * 4;    // transpose (C): dd, i-in-chunk

    float4 va, vb;
    {
        float f = g_fc[b * LC + lr];
        va = *(const float4*)(Eb + (size_t)lr * LQ + j0 + lc);
        va.x *= f; va.y *= f; va.z *= f; va.w *= f;
        vb = *(const float4*)(Cb + (size_t)bd * LC + bk);
    }

    for (int k0 = 0; k0 < LC; k0 += KC) {
        __syncthreads();
        *(float4*)&As[lr][lc] = va;
        Bs[bk + 0][bd] = vb.x;
        Bs[bk + 1][bd] = vb.y;
        Bs[bk + 2][bd] = vb.z;
        Bs[bk + 3][bd] = vb.w;
        __syncthreads();
        if (k0 + KC < LC) {
            float f = g_fc[b * LC + k0 + KC + lr];
            va = *(const float4*)(Eb + (size_t)(k0 + KC + lr) * LQ + j0 + lc);
            va.x *= f; va.y *= f; va.z *= f; va.w *= f;
            vb = *(const float4*)(Cb + (size_t)bd * LC + k0 + KC + bk);
        }
#pragma unroll
        for (int kk = 0; kk < KC; ++kk) {
            float av[8], bv[8];
            *(float4*)&av[0] = *(const float4*)&As[kk][tm * 4];
            *(float4*)&av[4] = *(const float4*)&As[kk][64 + tm * 4];
            *(float4*)&bv[0] = *(const float4*)&Bs[kk][tn * 4];
            *(float4*)&bv[4] = *(const float4*)&Bs[kk][64 + tn * 4];
#pragma unroll
            for (int r = 0; r < 8; ++r)
#pragma unroll
                for (int c = 0; c < 8; ++c) acc[r][c] = fmaf(av[r], bv[c], acc[r][c]);
        }
    }

    int jl[8];
#pragma unroll
    for (int t = 0; t < 4; ++t) { jl[t] = tm * 4 + t; jl[4 + t] = 64 + tm * 4 + t; }
    float cinv[8];
#pragma unroll
    for (int r = 0; r < 8; ++r) cinv[r] = 1.0f / g_colsum[b * LQ + j0 + jl[r]];
#pragma unroll
    for (int r = 0; r < 8; ++r) {
        float* mrow = g_M + ((size_t)b * LQ + j0 + jl[r]) * D;
        *(float4*)(mrow + tn * 4) =
            make_float4(acc[r][0] * cinv[r], acc[r][1] * cinv[r], acc[r][2] * cinv[r], acc[r][3] * cinv[r]);
        *(float4*)(mrow + 64 + tn * 4) =
            make_float4(acc[r][4] * cinv[r], acc[r][5] * cinv[r], acc[r][6] * cinv[r], acc[r][7] * cinv[r]);
    }
}

// ---------------- K5: A & Bmat fused + all 4 output channels -----------------
// grid (LC/128, B), K = LQ = 256, N = D = 128 (full)
__global__ __launch_bounds__(256) void k5_out(const float* __restrict__ C,
                                              const float* __restrict__ Q,
                                              float* __restrict__ out) {
    int b = blockIdx.y;
    int i0 = blockIdx.x * TS;

    __shared__ float As[KC][PADW];   // [k=j][i]   E*fq
    __shared__ float Bq[KC][PADW];   // [k=j][dd]  Q^T
    __shared__ float Bm[KC][PADW];   // [k=j][dd]  M
    __shared__ float fqs[LQ];

    int tid = threadIdx.x;
    int tm = tid & 15;   // i group
    int tn = tid >> 4;   // dd group
    fqs[tid] = g_fq[b * LQ + tid];

    float accA[8][8], accB[8][8];
#pragma unroll
    for (int r = 0; r < 8; ++r)
#pragma unroll
        for (int c = 0; c < 8; ++c) { accA[r][c] = 0.f; accB[r][c] = 0.f; }

    const float* Cb = C + (size_t)b * D * LC;
    const float* Qb = Q + (size_t)b * D * LQ;
    const float* Eb = g_E + (size_t)b * LC * LQ;
    const float* Mb = g_M + (size_t)b * LQ * D;

    int ai = tid >> 1, ak = (tid & 1) * 4;   // transpose (E over i, Q over dd)
    int lr = tid >> 5, lc = (tid & 31) * 4;  // direct (M)

    float4 ea, qa, ma;
    {
        ea = *(const float4*)(Eb + (size_t)(i0 + ai) * LQ + ak);
        qa = *(const float4*)(Qb + (size_t)ai * LQ + ak);
        ma = *(const float4*)(Mb + (size_t)lr * D + lc);
    }

    for (int k0 = 0; k0 < LQ; k0 += KC) {
        __syncthreads();
        As[ak + 0][ai] = ea.x * fqs[k0 + ak + 0];
        As[ak + 1][ai] = ea.y * fqs[k0 + ak + 1];
        As[ak + 2][ai] = ea.z * fqs[k0 + ak + 2];
        As[ak + 3][ai] = ea.w * fqs[k0 + ak + 3];
        Bq[ak + 0][ai] = qa.x;
        Bq[ak + 1][ai] = qa.y;
        Bq[ak + 2][ai] = qa.z;
        Bq[ak + 3][ai] = qa.w;
        *(float4*)&Bm[lr][lc] = ma;
        __syncthreads();
        if (k0 + KC < LQ) {
            ea = *(const float4*)(Eb + (size_t)(i0 + ai) * LQ + k0 + KC + ak);
            qa = *(const float4*)(Qb + (size_t)ai * LQ + k0 + KC + ak);
            ma = *(const float4*)(Mb + (size_t)(k0 + KC + lr) * D + lc);
        }
#pragma unroll
        for (int kk = 0; kk < KC; ++kk) {
            float av[8], qv[8], mv[8];
            *(float4*)&av[0] = *(const float4*)&As[kk][tm * 4];
            *(float4*)&av[4] = *(const float4*)&As[kk][64 + tm * 4];
            *(float4*)&qv[0] = *(const float4*)&Bq[kk][tn * 4];
            *(float4*)&qv[4] = *(const float4*)&Bq[kk][64 + tn * 4];
            *(float4*)&mv[0] = *(const float4*)&Bm[kk][tn * 4];
            *(float4*)&mv[4] = *(const float4*)&Bm[kk][64 + tn * 4];
#pragma unroll
            for (int r = 0; r < 8; ++r)
#pragma unroll
                for (int c = 0; c < 8; ++c) {
                    accA[r][c] = fmaf(av[r], qv[c], accA[r][c]);
                    accB[r][c] = fmaf(av[r], mv[c], accB[r][c]);
                }
        }
    }

    int il[8], ddl[8];
#pragma unroll
    for (int t = 0; t < 4; ++t) {
        il[t] = tm * 4 + t;  il[4 + t] = 64 + tm * 4 + t;
        ddl[t] = tn * 4 + t; ddl[4 + t] = 64 + tn * 4 + t;
    }
    float rinv[8];
#pragma unroll
    for (int r = 0; r < 8; ++r) rinv[r] = 1.0f / g_rowsum[b * LC + i0 + il[r]];

    size_t ob = (size_t)b * 4 * D * LC;
#pragma unroll
    for (int c = 0; c < 8; ++c) {
        int dd = ddl[c];
#pragma unroll
        for (int rq = 0; rq < 2; ++rq) {
            int ib = i0 + rq * 64 + tm * 4;
            int r0 = rq * 4;
            float4 c4 = *(const float4*)(Cb + (size_t)dd * LC + ib);
            float4 a4 = make_float4(accA[r0 + 0][c] * rinv[r0 + 0], accA[r0 + 1][c] * rinv[r0 + 1],
                                    accA[r0 + 2][c] * rinv[r0 + 2], accA[r0 + 3][c] * rinv[r0 + 3]);
            float4 b4 = make_float4(accB[r0 + 0][c] * rinv[r0 + 0], accB[r0 + 1][c] * rinv[r0 + 1],
                                    accB[r0 + 2][c] * rinv[r0 + 2], accB[r0 + 3][c] * rinv[r0 + 3]);
            *(float4*)(out + ob + (size_t)dd * LC + ib) = c4;                              // Ct
            *(float4*)(out + ob + (size_t)(D + dd) * LC + ib) = a4;                        // A
            *(float4*)(out + ob + (size_t)(2 * D + dd) * LC + ib) =
                make_float4(c4.x * a4.x, c4.y * a4.y, c4.z * a4.z, c4.w * a4.w);           // Ct*A
            *(float4*)(out + ob + (size_t)(3 * D + dd) * LC + ib) =
                make_float4(c4.x * b4.x, c4.y * b4.y, c4.z * b4.z, c4.w * b4.w);           // Ct*Bmat
        }
    }
}

// ---------------- launch ------------------------------------------------------
extern "C" void kernel_launch(void* const* d_in, const int* in_sizes, int n_in,
                              void* d_out, int out_size) {
    const float* C = (const float*)d_in[0];
    const float* Q = (const float*)d_in[1];
    const float* cmask = (const float*)d_in[2];
    const float* qmask = (const float*)d_in[3];
    const float* w = (const float*)d_in[4];
    float* out = (float*)d_out;

    k0_setup<<<(B * LC + B * LQ) / 256, 256>>>(C, Q, cmask, qmask, w);

    dim3 g1(LQ / TS, LC / TS, B);
    k1_score<<<g1, 256>>>(C, Q, w);

    dim3 g4(LQ / TS, B);
    k4_m<<<g4, 256>>>(C);

    dim3 g5(LC / TS, B);
    k5_out<<<g5, 256>>>(C, Q, out);
}

// round 4
// speedup vs baseline: 2.1189x; 1.0958x over previous
#include <cuda_runtime.h>
#include <math.h>

#define B    64
#define D    128
#define LC   1024
#define LQ   256
#define NEG_INF -1e30f
#define TS   128      // CTA tile (M and N)
#define KC   8        // K chunk
#define PADW 132      // padded smem row (floats)

typedef unsigned long long ull;

// packed fp32x2 FMA: acc.lo += a.lo*b.lo ; acc.hi += a.hi*b.hi
__device__ __forceinline__ void ffma2(ull& acc, ull a, ull b) {
    asm("fma.rn.f32x2 %0, %1, %2, %0;" : "+l"(acc) : "l"(a), "l"(b));
}
__device__ __forceinline__ ull dup2(float a) {
    ull r; asm("mov.b64 %0, {%1, %1};" : "=l"(r) : "f"(a)); return r;
}
__device__ __forceinline__ float lo32(ull v) { return __uint_as_float((unsigned)v); }
__device__ __forceinline__ float hi32(ull v) { return __uint_as_float((unsigned)(v >> 32)); }

// ---------------- scratch (device globals: no allocation allowed) ----------------
__device__ float g_E[(size_t)B * LC * LQ];   // exp(S), 64 MiB
__device__ float g_M[(size_t)B * LQ * D];    // S2^T @ Ct
__device__ float g_rowsum[B * LC];
__device__ float g_colsum[B * LQ];
__device__ float g_cw1[B * LC];
__device__ float g_qw2[B * LQ];
__device__ float g_fc[B * LC];               // exp((1-cmask)*NEG_INF)  (0 or 1)
__device__ float g_fq[B * LQ];               // exp((1-qmask)*NEG_INF)

// ---------------- K0: biases, mask factors, zero accumulators ----------------
__global__ void k0_setup(const float* __restrict__ C, const float* __restrict__ Q,
                         const float* __restrict__ cmask, const float* __restrict__ qmask,
                         const float* __restrict__ w) {
    int idx = blockIdx.x * 256 + threadIdx.x;
    if (idx < B * LC) {
        int b = idx >> 10;
        int i = idx & (LC - 1);
        const float* cp = C + (size_t)b * D * LC + i;
        float s = 0.f;
#pragma unroll 4
        for (int dd = 0; dd < D; ++dd) s = fmaf(cp[(size_t)dd * LC], w[dd], s);
        g_cw1[idx] = s;
        g_fc[idx] = expf((1.0f - cmask[idx]) * NEG_INF);
        g_rowsum[idx] = 0.f;
    } else {
        int t = idx - B * LC;
        if (t < B * LQ) {
            int b = t >> 8;
            int j = t & (LQ - 1);
            const float* qp = Q + (size_t)b * D * LQ + j;
            float s = 0.f;
#pragma unroll 4
            for (int dd = 0; dd < D; ++dd) s = fmaf(qp[(size_t)dd * LQ], w[D + dd], s);
            g_qw2[t] = s;
            g_fq[t] = expf((1.0f - qmask[t]) * NEG_INF);
            g_colsum[t] = 0.f;
        }
    }
}

// ---------------- K1: E = exp(S) + row/col exp-sums -------------------------
// grid (LQ/128, LC/128, B), 256 thr, 128x128 tile, 8x8 micro (FFMA2 on j-pairs)
__global__ __launch_bounds__(256) void k1_score(const float* __restrict__ C,
                                                const float* __restrict__ Q,
                                                const float* __restrict__ w) {
    int b = blockIdx.z;
    int i0 = blockIdx.y * TS;
    int j0 = blockIdx.x * TS;

    __shared__ __align__(16) float As[KC][PADW];   // [k=d][i]  C*w3
    __shared__ __align__(16) float Bs[KC][PADW];   // [k=d][j]  Q
    __shared__ float srow[TS], scol[TS];

    int tid = threadIdx.x;
    int tm = tid & 15;      // i group
    int tn = tid >> 4;      // j group
    if (tid < TS) srow[tid] = 0.f; else scol[tid - TS] = 0.f;

    ull acc[8][4];
#pragma unroll
    for (int r = 0; r < 8; ++r)
#pragma unroll
        for (int c = 0; c < 4; ++c) acc[r][c] = 0ull;

    const float* Cb = C + (size_t)b * D * LC;
    const float* Qb = Q + (size_t)b * D * LQ;

    int lr = tid >> 5;          // 0..7 (k within chunk)
    int lc = (tid & 31) * 4;    // 0..124

    float4 va, vb;
    {   // prefetch chunk 0
        float w3v = w[2 * D + lr];
        va = *(const float4*)(Cb + (size_t)lr * LC + i0 + lc);
        va.x *= w3v; va.y *= w3v; va.z *= w3v; va.w *= w3v;
        vb = *(const float4*)(Qb + (size_t)lr * LQ + j0 + lc);
    }

    for (int k0 = 0; k0 < D; k0 += KC) {
        __syncthreads();
        *(float4*)&As[lr][lc] = va;
        *(float4*)&Bs[lr][lc] = vb;
        __syncthreads();
        if (k0 + KC < D) {
            float w3v = w[2 * D + k0 + KC + lr];
            va = *(const float4*)(Cb + (size_t)(k0 + KC + lr) * LC + i0 + lc);
            va.x *= w3v; va.y *= w3v; va.z *= w3v; va.w *= w3v;
            vb = *(const float4*)(Qb + (size_t)(k0 + KC + lr) * LQ + j0 + lc);
        }
#pragma unroll
        for (int kk = 0; kk < KC; ++kk) {
            float4 a03 = *(const float4*)&As[kk][tm * 4];
            float4 a47 = *(const float4*)&As[kk][64 + tm * 4];
            ulonglong2 b01 = *(const ulonglong2*)&Bs[kk][tn * 4];
            ulonglong2 b23 = *(const ulonglong2*)&Bs[kk][64 + tn * 4];
            ull ad[8];
            ad[0] = dup2(a03.x); ad[1] = dup2(a03.y); ad[2] = dup2(a03.z); ad[3] = dup2(a03.w);
            ad[4] = dup2(a47.x); ad[5] = dup2(a47.y); ad[6] = dup2(a47.z); ad[7] = dup2(a47.w);
#pragma unroll
            for (int r = 0; r < 8; ++r) {
                ffma2(acc[r][0], ad[r], b01.x);
                ffma2(acc[r][1], ad[r], b01.y);
                ffma2(acc[r][2], ad[r], b23.x);
                ffma2(acc[r][3], ad[r], b23.y);
            }
        }
    }

    // ---- epilogue: biases, exp, store E, reduce row/col sums ----
    int il[8], jl[8];
#pragma unroll
    for (int t = 0; t < 4; ++t) {
        il[t] = tm * 4 + t;  il[4 + t] = 64 + tm * 4 + t;
        jl[t] = tn * 4 + t;  jl[4 + t] = 64 + tn * 4 + t;
    }
    float cw[8], fcv[8], qw[8], fqv[8];
#pragma unroll
    for (int r = 0; r < 8; ++r) { cw[r] = g_cw1[b * LC + i0 + il[r]]; fcv[r] = g_fc[b * LC + i0 + il[r]]; }
#pragma unroll
    for (int c = 0; c < 8; ++c) { qw[c] = g_qw2[b * LQ + j0 + jl[c]]; fqv[c] = g_fq[b * LQ + j0 + jl[c]]; }

    float rowp[8] = {0.f,0.f,0.f,0.f,0.f,0.f,0.f,0.f};
    float colp[8] = {0.f,0.f,0.f,0.f,0.f,0.f,0.f,0.f};
#pragma unroll
    for (int r = 0; r < 8; ++r) {
        float ev[8];
#pragma unroll
        for (int c = 0; c < 8; ++c) {
            float s = (c & 1) ? hi32(acc[r][c >> 1]) : lo32(acc[r][c >> 1]);
            float e = expf(s + cw[r] + qw[c]);
            ev[c] = e;
            rowp[r] = fmaf(e, fqv[c], rowp[r]);
            colp[c] = fmaf(e, fcv[r], colp[c]);
        }
        float* erow = g_E + ((size_t)b * LC + i0 + il[r]) * LQ + j0;
        *(float4*)(erow + tn * 4)      = make_float4(ev[0], ev[1], ev[2], ev[3]);
        *(float4*)(erow + 64 + tn * 4) = make_float4(ev[4], ev[5], ev[6], ev[7]);
    }
#pragma unroll
    for (int r = 0; r < 8; ++r) atomicAdd(&srow[il[r]], rowp[r]);
#pragma unroll
    for (int c = 0; c < 8; ++c) atomicAdd(&scol[jl[c]], colp[c]);
    __syncthreads();
    if (tid < TS) atomicAdd(&g_rowsum[b * LC + i0 + tid], srow[tid]);
    else          atomicAdd(&g_colsum[b * LQ + j0 + tid - TS], scol[tid - TS]);
}

// ---------------- K4: M[b,j,dd] = (sum_i E[i,j]*fc[i]*C[dd,i]) / colsum[j] ---
// grid (LQ/128, B), K = LC = 1024, N = D = 128 (full)
__global__ __launch_bounds__(256) void k4_m(const float* __restrict__ C) {
    int b = blockIdx.y;
    int j0 = blockIdx.x * TS;

    __shared__ __align__(16) float As[KC][PADW];   // [k=i][j]   E*fc
    __shared__ __align__(16) float Bs[KC][PADW];   // [k=i][dd]  C^T

    int tid = threadIdx.x;
    int tm = tid & 15;   // j group
    int tn = tid >> 4;   // dd group

    ull acc[8][4];
#pragma unroll
    for (int r = 0; r < 8; ++r)
#pragma unroll
        for (int c = 0; c < 4; ++c) acc[r][c] = 0ull;

    const float* Cb = C + (size_t)b * D * LC;
    const float* Eb = g_E + (size_t)b * LC * LQ;

    int lr = tid >> 5, lc = (tid & 31) * 4;   // direct (E): row=i-in-chunk, col=j
    int bd = tid >> 1, bk = (tid & 1) * 4;    // transpose (C): dd, i-in-chunk

    float4 va, vb;
    {
        float f = g_fc[b * LC + lr];
        va = *(const float4*)(Eb + (size_t)lr * LQ + j0 + lc);
        va.x *= f; va.y *= f; va.z *= f; va.w *= f;
        vb = *(const float4*)(Cb + (size_t)bd * LC + bk);
    }

    for (int k0 = 0; k0 < LC; k0 += KC) {
        __syncthreads();
        *(float4*)&As[lr][lc] = va;
        Bs[bk + 0][bd] = vb.x;
        Bs[bk + 1][bd] = vb.y;
        Bs[bk + 2][bd] = vb.z;
        Bs[bk + 3][bd] = vb.w;
        __syncthreads();
        if (k0 + KC < LC) {
            float f = g_fc[b * LC + k0 + KC + lr];
            va = *(const float4*)(Eb + (size_t)(k0 + KC + lr) * LQ + j0 + lc);
            va.x *= f; va.y *= f; va.z *= f; va.w *= f;
            vb = *(const float4*)(Cb + (size_t)bd * LC + k0 + KC + bk);
        }
#pragma unroll
        for (int kk = 0; kk < KC; ++kk) {
            float4 a03 = *(const float4*)&As[kk][tm * 4];
            float4 a47 = *(const float4*)&As[kk][64 + tm * 4];
            ulonglong2 b01 = *(const ulonglong2*)&Bs[kk][tn * 4];
            ulonglong2 b23 = *(const ulonglong2*)&Bs[kk][64 + tn * 4];
            ull ad[8];
            ad[0] = dup2(a03.x); ad[1] = dup2(a03.y); ad[2] = dup2(a03.z); ad[3] = dup2(a03.w);
            ad[4] = dup2(a47.x); ad[5] = dup2(a47.y); ad[6] = dup2(a47.z); ad[7] = dup2(a47.w);
#pragma unroll
            for (int r = 0; r < 8; ++r) {
                ffma2(acc[r][0], ad[r], b01.x);
                ffma2(acc[r][1], ad[r], b01.y);
                ffma2(acc[r][2], ad[r], b23.x);
                ffma2(acc[r][3], ad[r], b23.y);
            }
        }
    }

    int jl[8];
#pragma unroll
    for (int t = 0; t < 4; ++t) { jl[t] = tm * 4 + t; jl[4 + t] = 64 + tm * 4 + t; }
    float cinv[8];
#pragma unroll
    for (int r = 0; r < 8; ++r) cinv[r] = 1.0f / g_colsum[b * LQ + j0 + jl[r]];
#pragma unroll
    for (int r = 0; r < 8; ++r) {
        float* mrow = g_M + ((size_t)b * LQ + j0 + jl[r]) * D;
        *(float4*)(mrow + tn * 4) =
            make_float4(lo32(acc[r][0]) * cinv[r], hi32(acc[r][0]) * cinv[r],
                        lo32(acc[r][1]) * cinv[r], hi32(acc[r][1]) * cinv[r]);
        *(float4*)(mrow + 64 + tn * 4) =
            make_float4(lo32(acc[r][2]) * cinv[r], hi32(acc[r][2]) * cinv[r],
                        lo32(acc[r][3]) * cinv[r], hi32(acc[r][3]) * cinv[r]);
    }
}

// ---------------- K5: A & Bmat fused + all 4 output channels -----------------
// grid (LC/128, B), K = LQ = 256, N = D = 128 (full)
__global__ __launch_bounds__(256) void k5_out(const float* __restrict__ C,
                                              const float* __restrict__ Q,
                                              float* __restrict__ out) {
    int b = blockIdx.y;
    int i0 = blockIdx.x * TS;

    __shared__ __align__(16) float As[KC][PADW];   // [k=j][i]   E*fq
    __shared__ __align__(16) float Bq[KC][PADW];   // [k=j][dd]  Q^T
    __shared__ __align__(16) float Bm[KC][PADW];   // [k=j][dd]  M
    __shared__ float fqs[LQ];

    int tid = threadIdx.x;
    int tm = tid & 15;   // i group
    int tn = tid >> 4;   // dd group
    fqs[tid] = g_fq[b * LQ + tid];

    ull accA[8][4], accB[8][4];
#pragma unroll
    for (int r = 0; r < 8; ++r)
#pragma unroll
        for (int c = 0; c < 4; ++c) { accA[r][c] = 0ull; accB[r][c] = 0ull; }

    const float* Cb = C + (size_t)b * D * LC;
    const float* Qb = Q + (size_t)b * D * LQ;
    const float* Eb = g_E + (size_t)b * LC * LQ;
    const float* Mb = g_M + (size_t)b * LQ * D;

    int ai = tid >> 1, ak = (tid & 1) * 4;   // transpose (E over i, Q over dd)
    int lr = tid >> 5, lc = (tid & 31) * 4;  // direct (M)

    float4 ea, qa, ma;
    {
        ea = *(const float4*)(Eb + (size_t)(i0 + ai) * LQ + ak);
        qa = *(const float4*)(Qb + (size_t)ai * LQ + ak);
        ma = *(const float4*)(Mb + (size_t)lr * D + lc);
    }

    for (int k0 = 0; k0 < LQ; k0 += KC) {
        __syncthreads();
        As[ak + 0][ai] = ea.x * fqs[k0 + ak + 0];
        As[ak + 1][ai] = ea.y * fqs[k0 + ak + 1];
        As[ak + 2][ai] = ea.z * fqs[k0 + ak + 2];
        As[ak + 3][ai] = ea.w * fqs[k0 + ak + 3];
        Bq[ak + 0][ai] = qa.x;
        Bq[ak + 1][ai] = qa.y;
        Bq[ak + 2][ai] = qa.z;
        Bq[ak + 3][ai] = qa.w;
        *(float4*)&Bm[lr][lc] = ma;
        __syncthreads();
        if (k0 + KC < LQ) {
            ea = *(const float4*)(Eb + (size_t)(i0 + ai) * LQ + k0 + KC + ak);
            qa = *(const float4*)(Qb + (size_t)ai * LQ + k0 + KC + ak);
            ma = *(const float4*)(Mb + (size_t)(k0 + KC + lr) * D + lc);
        }
#pragma unroll
        for (int kk = 0; kk < KC; ++kk) {
            float4 a03 = *(const float4*)&As[kk][tm * 4];
            float4 a47 = *(const float4*)&As[kk][64 + tm * 4];
            ulonglong2 q01 = *(const ulonglong2*)&Bq[kk][tn * 4];
            ulonglong2 q23 = *(const ulonglong2*)&Bq[kk][64 + tn * 4];
            ulonglong2 m01 = *(const ulonglong2*)&Bm[kk][tn * 4];
            ulonglong2 m23 = *(const ulonglong2*)&Bm[kk][64 + tn * 4];
            ull ad[8];
            ad[0] = dup2(a03.x); ad[1] = dup2(a03.y); ad[2] = dup2(a03.z); ad[3] = dup2(a03.w);
            ad[4] = dup2(a47.x); ad[5] = dup2(a47.y); ad[6] = dup2(a47.z); ad[7] = dup2(a47.w);
#pragma unroll
            for (int r = 0; r < 8; ++r) {
                ffma2(accA[r][0], ad[r], q01.x);
                ffma2(accA[r][1], ad[r], q01.y);
                ffma2(accA[r][2], ad[r], q23.x);
                ffma2(accA[r][3], ad[r], q23.y);
                ffma2(accB[r][0], ad[r], m01.x);
                ffma2(accB[r][1], ad[r], m01.y);
                ffma2(accB[r][2], ad[r], m23.x);
                ffma2(accB[r][3], ad[r], m23.y);
            }
        }
    }

    int il[8], ddl[8];
#pragma unroll
    for (int t = 0; t < 4; ++t) {
        il[t] = tm * 4 + t;  il[4 + t] = 64 + tm * 4 + t;
        ddl[t] = tn * 4 + t; ddl[4 + t] = 64 + tn * 4 + t;
    }
    float rinv[8];
#pragma unroll
    for (int r = 0; r < 8; ++r) rinv[r] = 1.0f / g_rowsum[b * LC + i0 + il[r]];

    size_t ob = (size_t)b * 4 * D * LC;
#pragma unroll
    for (int c = 0; c < 8; ++c) {
        int dd = ddl[c];
        int c2 = c >> 1;
#pragma unroll
        for (int rq = 0; rq < 2; ++rq) {
            int ib = i0 + rq * 64 + tm * 4;
            int r0 = rq * 4;
            float4 c4 = *(const float4*)(Cb + (size_t)dd * LC + ib);
            float aA[4], aB[4];
#pragma unroll
            for (int t = 0; t < 4; ++t) {
                aA[t] = ((c & 1) ? hi32(accA[r0 + t][c2]) : lo32(accA[r0 + t][c2])) * rinv[r0 + t];
                aB[t] = ((c & 1) ? hi32(accB[r0 + t][c2]) : lo32(accB[r0 + t][c2])) * rinv[r0 + t];
            }
            float4 a4 = make_float4(aA[0], aA[1], aA[2], aA[3]);
            float4 b4 = make_float4(aB[0], aB[1], aB[2], aB[3]);
            *(float4*)(out + ob + (size_t)dd * LC + ib) = c4;                              // Ct
            *(float4*)(out + ob + (size_t)(D + dd) * LC + ib) = a4;                        // A
            *(float4*)(out + ob + (size_t)(2 * D + dd) * LC + ib) =
                make_float4(c4.x * a4.x, c4.y * a4.y, c4.z * a4.z, c4.w * a4.w);           // Ct*A
            *(float4*)(out + ob + (size_t)(3 * D + dd) * LC + ib) =
                make_float4(c4.x * b4.x, c4.y * b4.y, c4.z * b4.z, c4.w * b4.w);           // Ct*Bmat
        }
    }
}

// ---------------- launch ------------------------------------------------------
extern "C" void kernel_launch(void* const* d_in, const int* in_sizes, int n_in,
                              void* d_out, int out_size) {
    const float* C = (const float*)d_in[0];
    const float* Q = (const float*)d_in[1];
    const float* cmask = (const float*)d_in[2];
    const float* qmask = (const float*)d_in[3];
    const float* w = (const float*)d_in[4];
    float* out = (float*)d_out;

    k0_setup<<<(B * LC + B * LQ) / 256, 256>>>(C, Q, cmask, qmask, w);

    dim3 g1(LQ / TS, LC / TS, B);
    k1_score<<<g1, 256>>>(C, Q, w);

    dim3 g4(LQ / TS, B);
    k4_m<<<g4, 256>>>(C);

    dim3 g5(LC / TS, B);
    k5_out<<<g5, 256>>>(C, Q, out);
}